// round 1
// baseline (speedup 1.0000x reference)
#include <cuda_runtime.h>
#include <math.h>

// ---------------- problem constants ----------------
// B=8, H=W=128, C=128, HEADS=4, d=32, WS=8, SHIFT=4, HIDDEN=512
// tokens M = 8*128*128 = 131072, windows = 2048, N=64 per window
#define MTOK 131072

// ---------------- scratch (device globals; no allocs allowed) ----------------
static __device__ float g_ln1[MTOK * 128];   // LN1 + shifted window-partitioned
static __device__ float g_qkv[MTOK * 384];   // QKV
static __device__ float g_ao [MTOK * 128];   // attention output (heads concat)
static __device__ float g_x1 [MTOK * 128];   // x + proj (residual 1)
static __device__ float g_ln2[MTOK * 128];   // LN2 out
static __device__ float g_hid[(size_t)MTOK * 512]; // MLP hidden

// ---------------- LayerNorm (one warp per token), optional shift-gather ----------------
__global__ __launch_bounds__(256) void ln_kernel(
    const float* __restrict__ xin, const float* __restrict__ gam,
    const float* __restrict__ bet, float* __restrict__ out, int gather)
{
    int t = (blockIdx.x * blockDim.x + threadIdx.x) >> 5;  // token 0..131071
    int lane = threadIdx.x & 31;
    size_t src;
    if (gather) {
        int w = t >> 6, n = t & 63;
        int b = w >> 8, wrem = w & 255;
        int wi = wrem >> 4, wj = wrem & 15;
        int i = n >> 3, j = n & 7;
        int y  = (wi * 8 + i + 4) & 127;
        int xc = (wj * 8 + j + 4) & 127;
        src = ((size_t)b << 14) + (size_t)y * 128 + xc;
    } else {
        src = (size_t)t;
    }
    const float* p = xin + src * 128;
    float4 v = *(const float4*)(p + lane * 4);
    float s  = v.x + v.y + v.z + v.w;
    float sq = v.x * v.x + v.y * v.y + v.z * v.z + v.w * v.w;
    #pragma unroll
    for (int o = 16; o; o >>= 1) {
        s  += __shfl_xor_sync(0xffffffffu, s,  o);
        sq += __shfl_xor_sync(0xffffffffu, sq, o);
    }
    float mean = s * (1.f / 128.f);
    float var  = sq * (1.f / 128.f) - mean * mean;
    float rstd = rsqrtf(var + 1e-5f);
    float4 g4 = *(const float4*)(gam + lane * 4);
    float4 b4 = *(const float4*)(bet + lane * 4);
    float4 o;
    o.x = (v.x - mean) * rstd * g4.x + b4.x;
    o.y = (v.y - mean) * rstd * g4.y + b4.y;
    o.z = (v.z - mean) * rstd * g4.z + b4.z;
    o.w = (v.w - mean) * rstd * g4.w + b4.w;
    *(float4*)(out + (size_t)t * 128 + lane * 4) = o;
}

// ---------------- Generic NT SGEMM: D[M,N] = A[M,K] @ B[N,K]^T + bias ----------------
// mode 0: plain; 1: GELU(exact erf); 2: +res[m,n]; 3: scatter row (window-reverse
//         + unshift) and +res at scattered row (residual from original x)
__global__ __launch_bounds__(256) void gemm_nt(
    const float* __restrict__ A, const float* __restrict__ B,
    const float* __restrict__ bias, const float* __restrict__ res,
    float* __restrict__ D, int M, int N, int K, int mode)
{
    __shared__ float As[8][128];
    __shared__ float Bs[8][128];
    const int tid = threadIdx.x;
    const int m0 = blockIdx.y * 128;
    const int n0 = blockIdx.x * 128;
    const int tx = tid & 15, ty = tid >> 4;
    const int lr = tid >> 1;
    const int lc = (tid & 1) * 4;

    float acc[8][8];
    #pragma unroll
    for (int i = 0; i < 8; i++)
        #pragma unroll
        for (int j = 0; j < 8; j++) acc[i][j] = 0.f;

    const float* Ap = A + (size_t)(m0 + lr) * K + lc;
    const float* Bp = B + (size_t)(n0 + lr) * K + lc;

    for (int k0 = 0; k0 < K; k0 += 8) {
        float4 a4 = *(const float4*)(Ap + k0);
        float4 b4 = *(const float4*)(Bp + k0);
        As[lc + 0][lr] = a4.x; As[lc + 1][lr] = a4.y;
        As[lc + 2][lr] = a4.z; As[lc + 3][lr] = a4.w;
        Bs[lc + 0][lr] = b4.x; Bs[lc + 1][lr] = b4.y;
        Bs[lc + 2][lr] = b4.z; Bs[lc + 3][lr] = b4.w;
        __syncthreads();
        #pragma unroll
        for (int kk = 0; kk < 8; kk++) {
            float ra[8], rb[8];
            *(float4*)&ra[0] = *(const float4*)&As[kk][ty * 8];
            *(float4*)&ra[4] = *(const float4*)&As[kk][ty * 8 + 4];
            *(float4*)&rb[0] = *(const float4*)&Bs[kk][tx * 8];
            *(float4*)&rb[4] = *(const float4*)&Bs[kk][tx * 8 + 4];
            #pragma unroll
            for (int i = 0; i < 8; i++)
                #pragma unroll
                for (int j = 0; j < 8; j++)
                    acc[i][j] = fmaf(ra[i], rb[j], acc[i][j]);
        }
        __syncthreads();
    }

    #pragma unroll
    for (int i = 0; i < 8; i++) {
        int m = m0 + ty * 8 + i;
        size_t mo = (size_t)m;
        if (mode == 3) {
            int w = m >> 6, nt = m & 63;
            int b = w >> 8, wrem = w & 255;
            int wwi = wrem >> 4, wwj = wrem & 15;
            int ii = nt >> 3, jj = nt & 7;
            int yf = (wwi * 8 + ii + 4) & 127;
            int xf = (wwj * 8 + jj + 4) & 127;
            mo = ((size_t)b << 14) + (size_t)yf * 128 + xf;
        }
        #pragma unroll
        for (int j = 0; j < 8; j++) {
            int nn = n0 + tx * 8 + j;
            float v = acc[i][j] + bias[nn];
            if (mode == 1) {
                v = 0.5f * v * (1.f + erff(v * 0.70710678118654752f));
            } else if (mode == 2) {
                v += res[(size_t)m * N + nn];
            } else if (mode == 3) {
                v += res[mo * (size_t)N + nn];
            }
            D[mo * (size_t)N + nn] = v;
        }
    }
}

// ---------------- windowed attention: one block per (window, head) ----------------
__device__ __forceinline__ int reg3(int y) { return y < 120 ? 0 : (y < 124 ? 1 : 2); }

__global__ __launch_bounds__(64) void attn_kernel(
    const float* __restrict__ qkv, const float* __restrict__ rpb,
    float* __restrict__ ao)
{
    __shared__ float qs[64][33];
    __shared__ float ks[64][32];
    __shared__ float vs[64][32];
    __shared__ float ps[64][65];
    const int bid = blockIdx.x;
    const int w = bid >> 2, h = bid & 3;
    const int n = threadIdx.x;  // token row 0..63
    const float scale = 0.17677669529663689f;  // 32^-0.5

    for (int idx = n; idx < 2048; idx += 64) {
        int r = idx >> 5, c = idx & 31;
        const float* base = qkv + ((size_t)(w * 64 + r)) * 384 + h * 32 + c;
        qs[r][c] = base[0] * scale;
        ks[r][c] = base[128];
        vs[r][c] = base[256];
    }
    __syncthreads();

    float q[32];
    #pragma unroll
    for (int c = 0; c < 32; c++) q[c] = qs[n][c];

    const int i1 = n >> 3, j1 = n & 7;
    const int wrem = w & 255, wi = wrem >> 4, wj = wrem & 15;
    const int regn = 3 * reg3(wi * 8 + i1) + reg3(wj * 8 + j1);

    float mx = -1e30f;
    for (int m = 0; m < 64; m++) {
        float s = 0.f;
        #pragma unroll
        for (int c = 0; c < 32; c++) s = fmaf(q[c], ks[m][c], s);
        int i2 = m >> 3, j2 = m & 7;
        s += rpb[((i1 - i2 + 7) * 15 + (j1 - j2 + 7)) * 4 + h];
        int regm = 3 * reg3(wi * 8 + i2) + reg3(wj * 8 + j2);
        if (regm != regn) s -= 100.f;
        ps[n][m] = s;
        mx = fmaxf(mx, s);
    }
    float sum = 0.f;
    for (int m = 0; m < 64; m++) {
        float e = __expf(ps[n][m] - mx);
        ps[n][m] = e;
        sum += e;
    }
    float inv = 1.f / sum;

    float acc[32];
    #pragma unroll
    for (int c = 0; c < 32; c++) acc[c] = 0.f;
    for (int m = 0; m < 64; m++) {
        float p = ps[n][m];
        #pragma unroll
        for (int c = 0; c < 32; c++) acc[c] = fmaf(p, vs[m][c], acc[c]);
    }
    float* op = ao + ((size_t)(w * 64 + n)) * 128 + h * 32;
    #pragma unroll
    for (int c = 0; c < 32; c += 4) {
        float4 o4 = { acc[c] * inv, acc[c + 1] * inv, acc[c + 2] * inv, acc[c + 3] * inv };
        *(float4*)(op + c) = o4;
    }
}

// ---------------- launch ----------------
extern "C" void kernel_launch(void* const* d_in, const int* in_sizes, int n_in,
                              void* d_out, int out_size)
{
    const float* x      = (const float*)d_in[0];
    const float* rpb    = (const float*)d_in[1];
    const float* n1g    = (const float*)d_in[2];
    const float* n1b    = (const float*)d_in[3];
    const float* qkv_w  = (const float*)d_in[4];
    const float* qkv_b  = (const float*)d_in[5];
    const float* proj_w = (const float*)d_in[6];
    const float* proj_b = (const float*)d_in[7];
    const float* n2g    = (const float*)d_in[8];
    const float* n2b    = (const float*)d_in[9];
    const float* fc1_w  = (const float*)d_in[10];
    const float* fc1_b  = (const float*)d_in[11];
    const float* fc2_w  = (const float*)d_in[12];
    const float* fc2_b  = (const float*)d_in[13];
    float* out = (float*)d_out;

    float *ln1, *qkv, *ao, *x1, *ln2, *hid;
    cudaGetSymbolAddress((void**)&ln1, g_ln1);
    cudaGetSymbolAddress((void**)&qkv, g_qkv);
    cudaGetSymbolAddress((void**)&ao,  g_ao);
    cudaGetSymbolAddress((void**)&x1,  g_x1);
    cudaGetSymbolAddress((void**)&ln2, g_ln2);
    cudaGetSymbolAddress((void**)&hid, g_hid);

    const int M = MTOK;

    // 1) LN1 + cyclic shift + window partition
    ln_kernel<<<M / 8, 256>>>(x, n1g, n1b, ln1, 1);
    // 2) QKV: [M,384] = ln1[M,128] @ qkv_w[384,128]^T + b
    gemm_nt<<<dim3(3, M / 128), 256>>>(ln1, qkv_w, qkv_b, nullptr, qkv, M, 384, 128, 0);
    // 3) windowed attention with rel-pos bias + shift mask
    attn_kernel<<<8192, 64>>>(qkv, rpb, ao);
    // 4) proj + window-reverse + unshift + residual (scatter epilogue)
    gemm_nt<<<dim3(1, M / 128), 256>>>(ao, proj_w, proj_b, x, x1, M, 128, 128, 3);
    // 5) LN2
    ln_kernel<<<M / 8, 256>>>(x1, n2g, n2b, ln2, 0);
    // 6) fc1 + exact GELU
    gemm_nt<<<dim3(4, M / 128), 256>>>(ln2, fc1_w, fc1_b, nullptr, hid, M, 512, 128, 1);
    // 7) fc2 + residual -> final output
    gemm_nt<<<dim3(1, M / 128), 256>>>(hid, fc2_w, fc2_b, x1, out, M, 128, 512, 2);
}

// round 3
// speedup vs baseline: 3.2892x; 3.2892x over previous
#include <cuda_runtime.h>
#include <cuda_bf16.h>
#include <math.h>
#include <stdint.h>

// B=8, H=W=128, C=128, HEADS=4, d=32, WS=8, SHIFT=4, HIDDEN=512
#define MTOK 131072

// ---------------- scratch (device globals; no allocs allowed) ----------------
static __device__ unsigned short g_ln1[(size_t)MTOK * 128];  // bf16
static __device__ unsigned short g_qkv[(size_t)MTOK * 384];  // bf16
static __device__ unsigned short g_ao [(size_t)MTOK * 128];  // bf16
static __device__ float          g_x1 [(size_t)MTOK * 128];  // fp32 residual 1
static __device__ unsigned short g_ln2[(size_t)MTOK * 128];  // bf16
static __device__ unsigned short g_hid[(size_t)MTOK * 512];  // bf16
static __device__ unsigned short g_wq[384 * 128];
static __device__ unsigned short g_wp[128 * 128];
static __device__ unsigned short g_w1[512 * 128];
static __device__ unsigned short g_w2[128 * 512];

// ---------------- PTX helpers (sm_80+ features only; no 'a'-gated instrs) ----
static __device__ __forceinline__ uint32_t smem_u32(const void* p) {
    uint32_t a;
    asm("{ .reg .u64 t; cvta.to.shared.u64 t, %1; cvt.u32.u64 %0, t; }" : "=r"(a) : "l"(p));
    return a;
}
static __device__ __forceinline__ void cpa16(uint32_t s, const void* g) {
    asm volatile("cp.async.cg.shared.global [%0], [%1], 16;" :: "r"(s), "l"(g) : "memory");
}
static __device__ __forceinline__ void ldsm4(uint32_t* r, uint32_t addr) {
    asm volatile("ldmatrix.sync.aligned.m8n8.x4.shared.b16 {%0,%1,%2,%3}, [%4];"
                 : "=r"(r[0]), "=r"(r[1]), "=r"(r[2]), "=r"(r[3]) : "r"(addr));
}
static __device__ __forceinline__ void mma_bf16(float* c,
    uint32_t a0, uint32_t a1, uint32_t a2, uint32_t a3, uint32_t b0, uint32_t b1) {
    asm volatile(
        "mma.sync.aligned.m16n8k16.row.col.f32.bf16.bf16.f32 "
        "{%0,%1,%2,%3}, {%4,%5,%6,%7}, {%8,%9}, {%0,%1,%2,%3};"
        : "+f"(c[0]), "+f"(c[1]), "+f"(c[2]), "+f"(c[3])
        : "r"(a0), "r"(a1), "r"(a2), "r"(a3), "r"(b0), "r"(b1));
}

// ---------------- fp32 -> bf16 weight conversion ----------------
__global__ void f2bf(const float* __restrict__ s, unsigned short* __restrict__ d, int n4) {
    int i = blockIdx.x * 256 + threadIdx.x;
    if (i < n4) {
        float4 v = ((const float4*)s)[i];
        __nv_bfloat162 p0 = __floats2bfloat162_rn(v.x, v.y);
        __nv_bfloat162 p1 = __floats2bfloat162_rn(v.z, v.w);
        uint2 u;
        u.x = *reinterpret_cast<uint32_t*>(&p0);
        u.y = *reinterpret_cast<uint32_t*>(&p1);
        ((uint2*)d)[i] = u;
    }
}

// ---------------- LayerNorm (warp/token), optional shift-gather, bf16 out ------
__global__ __launch_bounds__(256) void ln_kernel(
    const float* __restrict__ xin, const float* __restrict__ gam,
    const float* __restrict__ bet, unsigned short* __restrict__ out, int gather)
{
    int t = (blockIdx.x * blockDim.x + threadIdx.x) >> 5;
    int lane = threadIdx.x & 31;
    size_t src;
    if (gather) {
        int w = t >> 6, n = t & 63;
        int b = w >> 8, wrem = w & 255;
        int wi = wrem >> 4, wj = wrem & 15;
        int i = n >> 3, j = n & 7;
        int y  = (wi * 8 + i + 4) & 127;
        int xc = (wj * 8 + j + 4) & 127;
        src = ((size_t)b << 14) + (size_t)y * 128 + xc;
    } else {
        src = (size_t)t;
    }
    float4 v = *(const float4*)(xin + src * 128 + lane * 4);
    float s  = v.x + v.y + v.z + v.w;
    float sq = v.x * v.x + v.y * v.y + v.z * v.z + v.w * v.w;
    #pragma unroll
    for (int o = 16; o; o >>= 1) {
        s  += __shfl_xor_sync(0xffffffffu, s,  o);
        sq += __shfl_xor_sync(0xffffffffu, sq, o);
    }
    float mean = s * (1.f / 128.f);
    float rstd = rsqrtf(sq * (1.f / 128.f) - mean * mean + 1e-5f);
    float4 g4 = *(const float4*)(gam + lane * 4);
    float4 b4 = *(const float4*)(bet + lane * 4);
    float ox = (v.x - mean) * rstd * g4.x + b4.x;
    float oy = (v.y - mean) * rstd * g4.y + b4.y;
    float oz = (v.z - mean) * rstd * g4.z + b4.z;
    float ow = (v.w - mean) * rstd * g4.w + b4.w;
    __nv_bfloat162 p0 = __floats2bfloat162_rn(ox, oy);
    __nv_bfloat162 p1 = __floats2bfloat162_rn(oz, ow);
    uint2 u;
    u.x = *reinterpret_cast<uint32_t*>(&p0);
    u.y = *reinterpret_cast<uint32_t*>(&p1);
    *(uint2*)(out + (size_t)t * 128 + lane * 4) = u;
}

// ---------------- bf16 HMMA GEMM: D[M,N] = A[M,K] @ B[N,K]^T + bias ----------
// mode 0: bf16 out; 1: GELU -> bf16 out; 2: +res fp32 out; 3: scatter +res fp32 out
// CTA 128x128, BK=64, double-buffered cp.async, 8 warps (2 x 4), warp 64x32.
#define GSMEM 65536
static __device__ __forceinline__ void stage_load(
    uint32_t sbase, const __nv_bfloat16* A, const __nv_bfloat16* B,
    int m0, int n0, int K, int kb, int tid)
{
    #pragma unroll
    for (int it = 0; it < 4; it++) {
        int idx = tid + (it << 8);
        int r = idx >> 3, q = idx & 7;
        uint32_t off = (uint32_t)((r << 7) | (q << 4));
        off ^= (off >> 3) & 0x70;   // SW128
        cpa16(sbase + off,           A + (size_t)(m0 + r) * K + kb * 64 + q * 8);
        cpa16(sbase + 16384u + off,  B + (size_t)(n0 + r) * K + kb * 64 + q * 8);
    }
    asm volatile("cp.async.commit_group;" ::: "memory");
}

__global__ __launch_bounds__(256) void gemm_mma(
    const unsigned short* __restrict__ Au, const unsigned short* __restrict__ Bu,
    const float* __restrict__ bias, const float* __restrict__ res,
    void* __restrict__ Dv, int M, int N, int K, int mode)
{
    extern __shared__ char dsm[];
    const __nv_bfloat16* A = (const __nv_bfloat16*)Au;
    const __nv_bfloat16* B = (const __nv_bfloat16*)Bu;
    uint32_t s0 = smem_u32(dsm);
    const int tid = threadIdx.x, lane = tid & 31, wid = tid >> 5;
    const int wm = wid >> 2, wn = wid & 3;
    const int m0 = blockIdx.y * 128, n0 = blockIdx.x * 128;

    float acc[4][4][4];
    #pragma unroll
    for (int a = 0; a < 4; a++)
        #pragma unroll
        for (int b = 0; b < 4; b++)
            #pragma unroll
            for (int c = 0; c < 4; c++) acc[a][b][c] = 0.f;

    const int lrow = (lane & 7) + ((lane >> 3) & 1) * 8;
    const int lhi  = lane >> 4;  // adds 1 to k-chunk for matrices 2,3

    const int KB = K >> 6;
    stage_load(s0, A, B, m0, n0, K, 0, tid);

    for (int kb = 0; kb < KB; kb++) {
        const uint32_t ab = s0 + (uint32_t)(kb & 1) * 32768u;
        const uint32_t bb = ab + 16384u;
        if (kb + 1 < KB) {
            stage_load(s0 + (uint32_t)((kb + 1) & 1) * 32768u, A, B, m0, n0, K, kb + 1, tid);
            asm volatile("cp.async.wait_group 1;" ::: "memory");
        } else {
            asm volatile("cp.async.wait_group 0;" ::: "memory");
        }
        __syncthreads();
        #pragma unroll
        for (int ks = 0; ks < 4; ks++) {
            uint32_t af[4][4], bf[2][4];
            const int chunk = ks * 2 + lhi;
            #pragma unroll
            for (int tm = 0; tm < 4; tm++) {
                int row = wm * 64 + tm * 16 + lrow;
                ldsm4(af[tm], ab + (uint32_t)(row * 128 + ((chunk ^ (row & 7)) << 4)));
            }
            #pragma unroll
            for (int t2 = 0; t2 < 2; t2++) {
                int row = wn * 32 + t2 * 16 + lrow;
                ldsm4(bf[t2], bb + (uint32_t)(row * 128 + ((chunk ^ (row & 7)) << 4)));
            }
            #pragma unroll
            for (int tm = 0; tm < 4; tm++)
                #pragma unroll
                for (int tn = 0; tn < 4; tn++)
                    mma_bf16(acc[tm][tn],
                             af[tm][0], af[tm][1], af[tm][2], af[tm][3],
                             bf[tn >> 1][tn & 1], bf[tn >> 1][2 + (tn & 1)]);
        }
        __syncthreads();
    }

    // ---- epilogue on register accumulators ----
    float2 bs[4];
    #pragma unroll
    for (int tn = 0; tn < 4; tn++)
        bs[tn] = *(const float2*)(bias + n0 + wn * 32 + tn * 8 + (lane & 3) * 2);

    #pragma unroll
    for (int tm = 0; tm < 4; tm++) {
        #pragma unroll
        for (int h = 0; h < 2; h++) {
            const int m = m0 + wm * 64 + tm * 16 + (lane >> 2) + h * 8;
            size_t mo = (size_t)m;
            if (mode == 3) {
                int w = m >> 6, nt = m & 63;
                int b = w >> 8, wrem = w & 255;
                int wwi = wrem >> 4, wwj = wrem & 15;
                int ii = nt >> 3, jj = nt & 7;
                int yf = (wwi * 8 + ii + 4) & 127;
                int xf = (wwj * 8 + jj + 4) & 127;
                mo = ((size_t)b << 14) + (size_t)yf * 128 + xf;
            }
            #pragma unroll
            for (int tn = 0; tn < 4; tn++) {
                const int nn = n0 + wn * 32 + tn * 8 + (lane & 3) * 2;
                float v0 = acc[tm][tn][h * 2 + 0] + bs[tn].x;
                float v1 = acc[tm][tn][h * 2 + 1] + bs[tn].y;
                if (mode == 1) {
                    v0 = 0.5f * v0 * (1.f + erff(v0 * 0.70710678118654752f));
                    v1 = 0.5f * v1 * (1.f + erff(v1 * 0.70710678118654752f));
                } else if (mode == 2) {
                    float2 r2 = *(const float2*)(res + (size_t)m * N + nn);
                    v0 += r2.x; v1 += r2.y;
                } else if (mode == 3) {
                    float2 r2 = *(const float2*)(res + mo * (size_t)N + nn);
                    v0 += r2.x; v1 += r2.y;
                }
                if (mode <= 1) {
                    __nv_bfloat162 p = __floats2bfloat162_rn(v0, v1);
                    *(uint32_t*)((__nv_bfloat16*)Dv + (size_t)m * N + nn) =
                        *reinterpret_cast<uint32_t*>(&p);
                } else {
                    *(float2*)((float*)Dv + mo * (size_t)N + nn) = make_float2(v0, v1);
                }
            }
        }
    }
}

// ---------------- windowed attention: one block per (window, head) -----------
__device__ __forceinline__ int reg3(int y) { return y < 120 ? 0 : (y < 124 ? 1 : 2); }

__global__ __launch_bounds__(64) void attn_kernel(
    const unsigned short* __restrict__ qkvu, const float* __restrict__ rpb,
    unsigned short* __restrict__ aou)
{
    __shared__ float qs[64][33];
    __shared__ float ks[64][32];
    __shared__ float vs[64][32];
    __shared__ float ps[64][65];
    const __nv_bfloat16* qkv = (const __nv_bfloat16*)qkvu;
    __nv_bfloat16* ao = (__nv_bfloat16*)aou;
    const int bid = blockIdx.x;
    const int w = bid >> 2, h = bid & 3;
    const int n = threadIdx.x;
    const float scale = 0.17677669529663689f;

    for (int idx = n; idx < 2048; idx += 64) {
        int r = idx >> 5, c = idx & 31;
        const __nv_bfloat16* base = qkv + (size_t)(w * 64 + r) * 384 + h * 32 + c;
        qs[r][c] = __bfloat162float(base[0]) * scale;
        ks[r][c] = __bfloat162float(base[128]);
        vs[r][c] = __bfloat162float(base[256]);
    }
    __syncthreads();

    float q[32];
    #pragma unroll
    for (int c = 0; c < 32; c++) q[c] = qs[n][c];

    const int i1 = n >> 3, j1 = n & 7;
    const int wrem = w & 255, wi = wrem >> 4, wj = wrem & 15;
    const int regn = 3 * reg3(wi * 8 + i1) + reg3(wj * 8 + j1);

    float mx = -1e30f;
    for (int m = 0; m < 64; m++) {
        float s = 0.f;
        #pragma unroll
        for (int c = 0; c < 32; c++) s = fmaf(q[c], ks[m][c], s);
        int i2 = m >> 3, j2 = m & 7;
        s += rpb[((i1 - i2 + 7) * 15 + (j1 - j2 + 7)) * 4 + h];
        int regm = 3 * reg3(wi * 8 + i2) + reg3(wj * 8 + j2);
        if (regm != regn) s -= 100.f;
        ps[n][m] = s;
        mx = fmaxf(mx, s);
    }
    float sum = 0.f;
    for (int m = 0; m < 64; m++) {
        float e = __expf(ps[n][m] - mx);
        ps[n][m] = e;
        sum += e;
    }
    float inv = 1.f / sum;

    float acc[32];
    #pragma unroll
    for (int c = 0; c < 32; c++) acc[c] = 0.f;
    for (int m = 0; m < 64; m++) {
        float p = ps[n][m];
        #pragma unroll
        for (int c = 0; c < 32; c++) acc[c] = fmaf(p, vs[m][c], acc[c]);
    }
    __nv_bfloat16* op = ao + (size_t)(w * 64 + n) * 128 + h * 32;
    #pragma unroll
    for (int c = 0; c < 32; c += 2)
        *(__nv_bfloat162*)(op + c) = __floats2bfloat162_rn(acc[c] * inv, acc[c + 1] * inv);
}

// ---------------- launch ----------------
extern "C" void kernel_launch(void* const* d_in, const int* in_sizes, int n_in,
                              void* d_out, int out_size)
{
    const float* x      = (const float*)d_in[0];
    const float* rpb    = (const float*)d_in[1];
    const float* n1g    = (const float*)d_in[2];
    const float* n1b    = (const float*)d_in[3];
    const float* qkv_w  = (const float*)d_in[4];
    const float* qkv_b  = (const float*)d_in[5];
    const float* proj_w = (const float*)d_in[6];
    const float* proj_b = (const float*)d_in[7];
    const float* n2g    = (const float*)d_in[8];
    const float* n2b    = (const float*)d_in[9];
    const float* fc1_w  = (const float*)d_in[10];
    const float* fc1_b  = (const float*)d_in[11];
    const float* fc2_w  = (const float*)d_in[12];
    const float* fc2_b  = (const float*)d_in[13];
    float* out = (float*)d_out;

    unsigned short *ln1, *qkv, *ao, *ln2, *hid, *wq, *wp, *w1, *w2;
    float *x1;
    cudaGetSymbolAddress((void**)&ln1, g_ln1);
    cudaGetSymbolAddress((void**)&qkv, g_qkv);
    cudaGetSymbolAddress((void**)&ao,  g_ao);
    cudaGetSymbolAddress((void**)&x1,  g_x1);
    cudaGetSymbolAddress((void**)&ln2, g_ln2);
    cudaGetSymbolAddress((void**)&hid, g_hid);
    cudaGetSymbolAddress((void**)&wq,  g_wq);
    cudaGetSymbolAddress((void**)&wp,  g_wp);
    cudaGetSymbolAddress((void**)&w1,  g_w1);
    cudaGetSymbolAddress((void**)&w2,  g_w2);

    cudaFuncSetAttribute(gemm_mma, cudaFuncAttributeMaxDynamicSharedMemorySize, GSMEM);

    const int M = MTOK;

    // weight conversions (bf16)
    f2bf<<<(384 * 128 / 4 + 255) / 256, 256>>>(qkv_w,  wq, 384 * 128 / 4);
    f2bf<<<(128 * 128 / 4 + 255) / 256, 256>>>(proj_w, wp, 128 * 128 / 4);
    f2bf<<<(512 * 128 / 4 + 255) / 256, 256>>>(fc1_w,  w1, 512 * 128 / 4);
    f2bf<<<(128 * 512 / 4 + 255) / 256, 256>>>(fc2_w,  w2, 128 * 512 / 4);

    // 1) LN1 + cyclic shift + window partition (bf16)
    ln_kernel<<<M / 8, 256>>>(x, n1g, n1b, ln1, 1);
    // 2) QKV GEMM: [M,384] bf16
    gemm_mma<<<dim3(3, M / 128), 256, GSMEM>>>(ln1, wq, qkv_b, nullptr, qkv, M, 384, 128, 0);
    // 3) windowed attention (bf16 in/out)
    attn_kernel<<<8192, 64>>>(qkv, rpb, ao);
    // 4) proj GEMM + window-reverse + unshift + residual (fp32 out)
    gemm_mma<<<dim3(1, M / 128), 256, GSMEM>>>(ao, wp, proj_b, x, x1, M, 128, 128, 3);
    // 5) LN2 (bf16)
    ln_kernel<<<M / 8, 256>>>(x1, n2g, n2b, ln2, 0);
    // 6) fc1 + GELU (bf16 out)
    gemm_mma<<<dim3(4, M / 128), 256, GSMEM>>>(ln2, w1, fc1_b, nullptr, hid, M, 512, 128, 1);
    // 7) fc2 + residual -> final fp32 output
    gemm_mma<<<dim3(1, M / 128), 256, GSMEM>>>(hid, w2, fc2_b, x1, out, M, 128, 512, 2);
}

// round 4
// speedup vs baseline: 5.0623x; 1.5391x over previous
#include <cuda_runtime.h>
#include <cuda_bf16.h>
#include <math.h>
#include <stdint.h>

// B=8, H=W=128, C=128, HEADS=4, d=32, WS=8, SHIFT=4, HIDDEN=512
#define MTOK 131072

// ---------------- scratch (device globals; no allocs allowed) ----------------
static __device__ unsigned short g_ln1[(size_t)MTOK * 128];  // bf16
static __device__ unsigned short g_qkv[(size_t)MTOK * 384];  // bf16
static __device__ unsigned short g_ao [(size_t)MTOK * 128];  // bf16
static __device__ float          g_x1 [(size_t)MTOK * 128];  // fp32 residual 1
static __device__ unsigned short g_ln2[(size_t)MTOK * 128];  // bf16
static __device__ unsigned short g_hid[(size_t)MTOK * 512];  // bf16
static __device__ unsigned short g_wq[384 * 128];
static __device__ unsigned short g_wp[128 * 128];
static __device__ unsigned short g_w1[512 * 128];
static __device__ unsigned short g_w2[128 * 512];

// ---------------- PTX helpers (sm_80+ features only) ----------------
static __device__ __forceinline__ uint32_t smem_u32(const void* p) {
    uint32_t a;
    asm("{ .reg .u64 t; cvta.to.shared.u64 t, %1; cvt.u32.u64 %0, t; }" : "=r"(a) : "l"(p));
    return a;
}
static __device__ __forceinline__ void cpa16(uint32_t s, const void* g) {
    asm volatile("cp.async.cg.shared.global [%0], [%1], 16;" :: "r"(s), "l"(g) : "memory");
}
static __device__ __forceinline__ void ldsm4(uint32_t* r, uint32_t addr) {
    asm volatile("ldmatrix.sync.aligned.m8n8.x4.shared.b16 {%0,%1,%2,%3}, [%4];"
                 : "=r"(r[0]), "=r"(r[1]), "=r"(r[2]), "=r"(r[3]) : "r"(addr));
}
static __device__ __forceinline__ void ldsm4t(uint32_t* r, uint32_t addr) {
    asm volatile("ldmatrix.sync.aligned.m8n8.x4.trans.shared.b16 {%0,%1,%2,%3}, [%4];"
                 : "=r"(r[0]), "=r"(r[1]), "=r"(r[2]), "=r"(r[3]) : "r"(addr));
}
static __device__ __forceinline__ void mma_bf16(float* c,
    uint32_t a0, uint32_t a1, uint32_t a2, uint32_t a3, uint32_t b0, uint32_t b1) {
    asm volatile(
        "mma.sync.aligned.m16n8k16.row.col.f32.bf16.bf16.f32 "
        "{%0,%1,%2,%3}, {%4,%5,%6,%7}, {%8,%9}, {%0,%1,%2,%3};"
        : "+f"(c[0]), "+f"(c[1]), "+f"(c[2]), "+f"(c[3])
        : "r"(a0), "r"(a1), "r"(a2), "r"(a3), "r"(b0), "r"(b1));
}
static __device__ __forceinline__ uint32_t packbf(float a, float b) {
    __nv_bfloat162 p = __floats2bfloat162_rn(a, b);
    return *reinterpret_cast<uint32_t*>(&p);
}

// ---------------- merged fp32 -> bf16 weight conversion ----------------
__global__ __launch_bounds__(256) void f2bf_all(
    const float* __restrict__ s0, unsigned short* __restrict__ d0,
    const float* __restrict__ s1, unsigned short* __restrict__ d1,
    const float* __restrict__ s2, unsigned short* __restrict__ d2,
    const float* __restrict__ s3, unsigned short* __restrict__ d3)
{
    int i = blockIdx.x * 256 + threadIdx.x;   // 0..49151 float4 groups
    const float* s; unsigned short* d; int o;
    if (i < 12288)      { s = s0; d = d0; o = i; }
    else if (i < 16384) { s = s1; d = d1; o = i - 12288; }
    else if (i < 32768) { s = s2; d = d2; o = i - 16384; }
    else                { s = s3; d = d3; o = i - 32768; }
    float4 v = ((const float4*)s)[o];
    uint2 u;
    u.x = packbf(v.x, v.y);
    u.y = packbf(v.z, v.w);
    ((uint2*)d)[o] = u;
}

// ---------------- LayerNorm (warp/token), optional shift-gather, bf16 out ------
__global__ __launch_bounds__(256) void ln_kernel(
    const float* __restrict__ xin, const float* __restrict__ gam,
    const float* __restrict__ bet, unsigned short* __restrict__ out, int gather)
{
    int t = (blockIdx.x * blockDim.x + threadIdx.x) >> 5;
    int lane = threadIdx.x & 31;
    size_t src;
    if (gather) {
        int w = t >> 6, n = t & 63;
        int b = w >> 8, wrem = w & 255;
        int wi = wrem >> 4, wj = wrem & 15;
        int i = n >> 3, j = n & 7;
        int y  = (wi * 8 + i + 4) & 127;
        int xc = (wj * 8 + j + 4) & 127;
        src = ((size_t)b << 14) + (size_t)y * 128 + xc;
    } else {
        src = (size_t)t;
    }
    float4 v = *(const float4*)(xin + src * 128 + lane * 4);
    float s  = v.x + v.y + v.z + v.w;
    float sq = v.x * v.x + v.y * v.y + v.z * v.z + v.w * v.w;
    #pragma unroll
    for (int o = 16; o; o >>= 1) {
        s  += __shfl_xor_sync(0xffffffffu, s,  o);
        sq += __shfl_xor_sync(0xffffffffu, sq, o);
    }
    float mean = s * (1.f / 128.f);
    float rstd = rsqrtf(sq * (1.f / 128.f) - mean * mean + 1e-5f);
    float4 g4 = *(const float4*)(gam + lane * 4);
    float4 b4 = *(const float4*)(bet + lane * 4);
    uint2 u;
    u.x = packbf((v.x - mean) * rstd * g4.x + b4.x, (v.y - mean) * rstd * g4.y + b4.y);
    u.y = packbf((v.z - mean) * rstd * g4.z + b4.z, (v.w - mean) * rstd * g4.w + b4.w);
    *(uint2*)(out + (size_t)t * 128 + lane * 4) = u;
}

// ---------------- bf16 HMMA GEMM: D[M,N] = A[M,K] @ B[N,K]^T + bias ----------
// mode 0: bf16 out; 1: GELU -> bf16 out; 2: +res fp32 out; 3: scatter +res fp32 out
#define GSMEM 65536
static __device__ __forceinline__ void stage_load(
    uint32_t sbase, const __nv_bfloat16* A, const __nv_bfloat16* B,
    int m0, int n0, int K, int kb, int tid)
{
    #pragma unroll
    for (int it = 0; it < 4; it++) {
        int idx = tid + (it << 8);
        int r = idx >> 3, q = idx & 7;
        uint32_t off = (uint32_t)((r << 7) | (q << 4));
        off ^= (off >> 3) & 0x70;   // SW128
        cpa16(sbase + off,           A + (size_t)(m0 + r) * K + kb * 64 + q * 8);
        cpa16(sbase + 16384u + off,  B + (size_t)(n0 + r) * K + kb * 64 + q * 8);
    }
    asm volatile("cp.async.commit_group;" ::: "memory");
}

__global__ __launch_bounds__(256) void gemm_mma(
    const unsigned short* __restrict__ Au, const unsigned short* __restrict__ Bu,
    const float* __restrict__ bias, const float* __restrict__ res,
    void* __restrict__ Dv, int M, int N, int K, int mode)
{
    extern __shared__ char dsm[];
    const __nv_bfloat16* A = (const __nv_bfloat16*)Au;
    const __nv_bfloat16* B = (const __nv_bfloat16*)Bu;
    uint32_t s0 = smem_u32(dsm);
    const int tid = threadIdx.x, lane = tid & 31, wid = tid >> 5;
    const int wm = wid >> 2, wn = wid & 3;
    const int m0 = blockIdx.y * 128, n0 = blockIdx.x * 128;

    float acc[4][4][4];
    #pragma unroll
    for (int a = 0; a < 4; a++)
        #pragma unroll
        for (int b = 0; b < 4; b++)
            #pragma unroll
            for (int c = 0; c < 4; c++) acc[a][b][c] = 0.f;

    const int lrow = (lane & 7) + ((lane >> 3) & 1) * 8;
    const int lhi  = lane >> 4;

    const int KB = K >> 6;
    stage_load(s0, A, B, m0, n0, K, 0, tid);

    for (int kb = 0; kb < KB; kb++) {
        const uint32_t ab = s0 + (uint32_t)(kb & 1) * 32768u;
        const uint32_t bb = ab + 16384u;
        if (kb + 1 < KB) {
            stage_load(s0 + (uint32_t)((kb + 1) & 1) * 32768u, A, B, m0, n0, K, kb + 1, tid);
            asm volatile("cp.async.wait_group 1;" ::: "memory");
        } else {
            asm volatile("cp.async.wait_group 0;" ::: "memory");
        }
        __syncthreads();
        #pragma unroll
        for (int ks = 0; ks < 4; ks++) {
            uint32_t af[4][4], bf[2][4];
            const int chunk = ks * 2 + lhi;
            #pragma unroll
            for (int tm = 0; tm < 4; tm++) {
                int row = wm * 64 + tm * 16 + lrow;
                ldsm4(af[tm], ab + (uint32_t)(row * 128 + ((chunk ^ (row & 7)) << 4)));
            }
            #pragma unroll
            for (int t2 = 0; t2 < 2; t2++) {
                int row = wn * 32 + t2 * 16 + lrow;
                ldsm4(bf[t2], bb + (uint32_t)(row * 128 + ((chunk ^ (row & 7)) << 4)));
            }
            #pragma unroll
            for (int tm = 0; tm < 4; tm++)
                #pragma unroll
                for (int tn = 0; tn < 4; tn++)
                    mma_bf16(acc[tm][tn],
                             af[tm][0], af[tm][1], af[tm][2], af[tm][3],
                             bf[tn >> 1][tn & 1], bf[tn >> 1][2 + (tn & 1)]);
        }
        __syncthreads();
    }

    float2 bs[4];
    #pragma unroll
    for (int tn = 0; tn < 4; tn++)
        bs[tn] = *(const float2*)(bias + n0 + wn * 32 + tn * 8 + (lane & 3) * 2);

    #pragma unroll
    for (int tm = 0; tm < 4; tm++) {
        #pragma unroll
        for (int h = 0; h < 2; h++) {
            const int m = m0 + wm * 64 + tm * 16 + (lane >> 2) + h * 8;
            size_t mo = (size_t)m;
            if (mode == 3) {
                int w = m >> 6, nt = m & 63;
                int b = w >> 8, wrem = w & 255;
                int wwi = wrem >> 4, wwj = wrem & 15;
                int ii = nt >> 3, jj = nt & 7;
                int yf = (wwi * 8 + ii + 4) & 127;
                int xf = (wwj * 8 + jj + 4) & 127;
                mo = ((size_t)b << 14) + (size_t)yf * 128 + xf;
            }
            #pragma unroll
            for (int tn = 0; tn < 4; tn++) {
                const int nn = n0 + wn * 32 + tn * 8 + (lane & 3) * 2;
                float v0 = acc[tm][tn][h * 2 + 0] + bs[tn].x;
                float v1 = acc[tm][tn][h * 2 + 1] + bs[tn].y;
                if (mode == 1) {
                    v0 = 0.5f * v0 * (1.f + erff(v0 * 0.70710678118654752f));
                    v1 = 0.5f * v1 * (1.f + erff(v1 * 0.70710678118654752f));
                } else if (mode == 2) {
                    float2 r2 = *(const float2*)(res + (size_t)m * N + nn);
                    v0 += r2.x; v1 += r2.y;
                } else if (mode == 3) {
                    float2 r2 = *(const float2*)(res + mo * (size_t)N + nn);
                    v0 += r2.x; v1 += r2.y;
                }
                if (mode <= 1) {
                    *(uint32_t*)((__nv_bfloat16*)Dv + (size_t)m * N + nn) = packbf(v0, v1);
                } else {
                    *(float2*)((float*)Dv + mo * (size_t)N + nn) = make_float2(v0, v1);
                }
            }
        }
    }
}

// ---------------- HMMA windowed attention: block = (window, head), 4 warps ----
__device__ __forceinline__ int reg3(int y) { return y < 120 ? 0 : (y < 124 ? 1 : 2); }

__global__ __launch_bounds__(128) void attn_mma(
    const unsigned short* __restrict__ qkvu, const float* __restrict__ rpb,
    unsigned short* __restrict__ aou)
{
    // stride-80B rows (40 bf16): conflict-free ldmatrix (banks (20r)%32 distinct)
    __shared__ __align__(16) unsigned short qs[64 * 40];
    __shared__ __align__(16) unsigned short ks[64 * 40];
    __shared__ __align__(16) unsigned short vs[64 * 40];
    __shared__ float rpbs[900];
    __shared__ int  regtok[64];
    const __nv_bfloat16* qkv = (const __nv_bfloat16*)qkvu;
    const int tid = threadIdx.x, lane = tid & 31, wm = tid >> 5;
    const int w = blockIdx.x >> 2, h = blockIdx.x & 3;

    // stage q/k/v head-slice: 768 16B-chunks
    {
        const size_t tokbase = (size_t)w * 64;
        #pragma unroll
        for (int it = 0; it < 6; it++) {
            int c = tid + it * 128;
            int mat = c >> 8, rem = c & 255;
            int row = rem >> 2, ch = rem & 3;
            const uint4 v = *(const uint4*)(qkv + (tokbase + row) * 384 + mat * 128 + h * 32 + ch * 8);
            unsigned short* dst = (mat == 0 ? qs : (mat == 1 ? ks : vs));
            *(uint4*)(dst + row * 40 + ch * 8) = v;
        }
        #pragma unroll
        for (int it = 0; it < 8; it++) {
            int idx = tid + it * 128;
            if (idx < 900) rpbs[idx] = rpb[idx];
        }
        if (tid < 64) {
            int wrem = w & 255, wi = wrem >> 4, wj = wrem & 15;
            regtok[tid] = 3 * reg3(wi * 8 + (tid >> 3)) + reg3(wj * 8 + (tid & 7));
        }
    }
    __syncthreads();

    const uint32_t qb = smem_u32(qs), kb_ = smem_u32(ks), vb_ = smem_u32(vs);
    const int lr8 = (lane & 7) + ((lane >> 3) & 1) * 8;
    const uint32_t lh16 = ((lane >> 4) & 1) * 16;

    // Q fragments: rows wm*16.., k=32 (2 chunks)
    uint32_t qa[2][4];
    {
        uint32_t addr = qb + (uint32_t)((wm * 16 + lr8) * 80) + lh16;
        ldsm4(qa[0], addr);
        ldsm4(qa[1], addr + 32);
    }
    // K fragments: 4 n16 groups x 2 k16 chunks
    uint32_t kf[4][2][4];
    #pragma unroll
    for (int nt = 0; nt < 4; nt++) {
        uint32_t addr = kb_ + (uint32_t)((nt * 16 + lr8) * 80) + lh16;
        ldsm4(kf[nt][0], addr);
        ldsm4(kf[nt][1], addr + 32);
    }

    // S = Q K^T
    float sc[8][4];
    #pragma unroll
    for (int i = 0; i < 8; i++)
        #pragma unroll
        for (int c = 0; c < 4; c++) sc[i][c] = 0.f;
    #pragma unroll
    for (int nt8 = 0; nt8 < 8; nt8++) {
        const int nt = nt8 >> 1, ii = nt8 & 1;
        mma_bf16(sc[nt8], qa[0][0], qa[0][1], qa[0][2], qa[0][3], kf[nt][0][ii], kf[nt][0][2 + ii]);
        mma_bf16(sc[nt8], qa[1][0], qa[1][1], qa[1][2], qa[1][3], kf[nt][1][ii], kf[nt][1][2 + ii]);
    }

    // scale + rel-pos bias + shift mask
    const float scale = 0.17677669529663689f;
    const int r0 = wm * 16 + (lane >> 2), r1 = r0 + 8;
    const int rg0 = regtok[r0], rg1 = regtok[r1];
    const int i1a = r0 >> 3, j1a = r0 & 7, i1b = r1 >> 3, j1b = r1 & 7;
    #pragma unroll
    for (int nt8 = 0; nt8 < 8; nt8++) {
        #pragma unroll
        for (int c = 0; c < 4; c++) {
            const int col = nt8 * 8 + (lane & 3) * 2 + (c & 1);
            const int i2 = col >> 3, j2 = col & 7;
            const int rgc = regtok[col];
            float v = sc[nt8][c] * scale;
            if (c < 2) {
                v += rpbs[((i1a - i2 + 7) * 15 + (j1a - j2 + 7)) * 4 + h];
                if (rgc != rg0) v -= 100.f;
            } else {
                v += rpbs[((i1b - i2 + 7) * 15 + (j1b - j2 + 7)) * 4 + h];
                if (rgc != rg1) v -= 100.f;
            }
            sc[nt8][c] = v;
        }
    }

    // row softmax (rows r0, r1 live in quad lanes lane^1, lane^2)
    float mx0 = -1e30f, mx1 = -1e30f;
    #pragma unroll
    for (int nt8 = 0; nt8 < 8; nt8++) {
        mx0 = fmaxf(mx0, fmaxf(sc[nt8][0], sc[nt8][1]));
        mx1 = fmaxf(mx1, fmaxf(sc[nt8][2], sc[nt8][3]));
    }
    #pragma unroll
    for (int o = 1; o <= 2; o <<= 1) {
        mx0 = fmaxf(mx0, __shfl_xor_sync(0xffffffffu, mx0, o));
        mx1 = fmaxf(mx1, __shfl_xor_sync(0xffffffffu, mx1, o));
    }
    float sm0 = 0.f, sm1 = 0.f;
    #pragma unroll
    for (int nt8 = 0; nt8 < 8; nt8++) {
        sc[nt8][0] = __expf(sc[nt8][0] - mx0);
        sc[nt8][1] = __expf(sc[nt8][1] - mx0);
        sc[nt8][2] = __expf(sc[nt8][2] - mx1);
        sc[nt8][3] = __expf(sc[nt8][3] - mx1);
        sm0 += sc[nt8][0] + sc[nt8][1];
        sm1 += sc[nt8][2] + sc[nt8][3];
    }
    #pragma unroll
    for (int o = 1; o <= 2; o <<= 1) {
        sm0 += __shfl_xor_sync(0xffffffffu, sm0, o);
        sm1 += __shfl_xor_sync(0xffffffffu, sm1, o);
    }
    const float inv0 = 1.f / sm0, inv1 = 1.f / sm1;

    // O = P V   (P fragments come straight from S's C layout)
    float oc[4][4];
    #pragma unroll
    for (int nt = 0; nt < 4; nt++)
        #pragma unroll
        for (int c = 0; c < 4; c++) oc[nt][c] = 0.f;
    #pragma unroll
    for (int kc = 0; kc < 4; kc++) {
        const uint32_t a0 = packbf(sc[2 * kc][0],     sc[2 * kc][1]);
        const uint32_t a1 = packbf(sc[2 * kc][2],     sc[2 * kc][3]);
        const uint32_t a2 = packbf(sc[2 * kc + 1][0], sc[2 * kc + 1][1]);
        const uint32_t a3 = packbf(sc[2 * kc + 1][2], sc[2 * kc + 1][3]);
        uint32_t vf0[4], vf1[4];
        const uint32_t vaddr = vb_ + (uint32_t)((kc * 16 + lr8) * 80) + lh16;
        ldsm4t(vf0, vaddr);        // dims 0-15
        ldsm4t(vf1, vaddr + 32);   // dims 16-31
        mma_bf16(oc[0], a0, a1, a2, a3, vf0[0], vf0[1]);
        mma_bf16(oc[1], a0, a1, a2, a3, vf0[2], vf0[3]);
        mma_bf16(oc[2], a0, a1, a2, a3, vf1[0], vf1[1]);
        mma_bf16(oc[3], a0, a1, a2, a3, vf1[2], vf1[3]);
    }

    // write out: token rows r0/r1, channels h*32 + nt*8 + (lane&3)*2
    __nv_bfloat16* ao = (__nv_bfloat16*)aou;
    const size_t t0 = (size_t)w * 64;
    #pragma unroll
    for (int nt = 0; nt < 4; nt++) {
        const int ch = h * 32 + nt * 8 + (lane & 3) * 2;
        *(uint32_t*)(ao + (t0 + r0) * 128 + ch) = packbf(oc[nt][0] * inv0, oc[nt][1] * inv0);
        *(uint32_t*)(ao + (t0 + r1) * 128 + ch) = packbf(oc[nt][2] * inv1, oc[nt][3] * inv1);
    }
}

// ---------------- launch ----------------
extern "C" void kernel_launch(void* const* d_in, const int* in_sizes, int n_in,
                              void* d_out, int out_size)
{
    const float* x      = (const float*)d_in[0];
    const float* rpb    = (const float*)d_in[1];
    const float* n1g    = (const float*)d_in[2];
    const float* n1b    = (const float*)d_in[3];
    const float* qkv_w  = (const float*)d_in[4];
    const float* qkv_b  = (const float*)d_in[5];
    const float* proj_w = (const float*)d_in[6];
    const float* proj_b = (const float*)d_in[7];
    const float* n2g    = (const float*)d_in[8];
    const float* n2b    = (const float*)d_in[9];
    const float* fc1_w  = (const float*)d_in[10];
    const float* fc1_b  = (const float*)d_in[11];
    const float* fc2_w  = (const float*)d_in[12];
    const float* fc2_b  = (const float*)d_in[13];
    float* out = (float*)d_out;

    unsigned short *ln1, *qkv, *ao, *ln2, *hid, *wq, *wp, *w1, *w2;
    float *x1;
    cudaGetSymbolAddress((void**)&ln1, g_ln1);
    cudaGetSymbolAddress((void**)&qkv, g_qkv);
    cudaGetSymbolAddress((void**)&ao,  g_ao);
    cudaGetSymbolAddress((void**)&x1,  g_x1);
    cudaGetSymbolAddress((void**)&ln2, g_ln2);
    cudaGetSymbolAddress((void**)&hid, g_hid);
    cudaGetSymbolAddress((void**)&wq,  g_wq);
    cudaGetSymbolAddress((void**)&wp,  g_wp);
    cudaGetSymbolAddress((void**)&w1,  g_w1);
    cudaGetSymbolAddress((void**)&w2,  g_w2);

    cudaFuncSetAttribute(gemm_mma, cudaFuncAttributeMaxDynamicSharedMemorySize, GSMEM);

    const int M = MTOK;

    // merged weight conversion (one launch)
    f2bf_all<<<192, 256>>>(qkv_w, wq, proj_w, wp, fc1_w, w1, fc2_w, w2);

    // 1) LN1 + cyclic shift + window partition (bf16)
    ln_kernel<<<M / 8, 256>>>(x, n1g, n1b, ln1, 1);
    // 2) QKV GEMM: [M,384] bf16
    gemm_mma<<<dim3(3, M / 128), 256, GSMEM>>>(ln1, wq, qkv_b, nullptr, qkv, M, 384, 128, 0);
    // 3) HMMA windowed attention
    attn_mma<<<8192, 128>>>(qkv, rpb, ao);
    // 4) proj GEMM + window-reverse + unshift + residual (fp32 out)
    gemm_mma<<<dim3(1, M / 128), 256, GSMEM>>>(ao, wp, proj_b, x, x1, M, 128, 128, 3);
    // 5) LN2 (bf16)
    ln_kernel<<<M / 8, 256>>>(x1, n2g, n2b, ln2, 0);
    // 6) fc1 + GELU (bf16 out)
    gemm_mma<<<dim3(4, M / 128), 256, GSMEM>>>(ln2, w1, fc1_b, nullptr, hid, M, 512, 128, 1);
    // 7) fc2 + residual -> final fp32 output
    gemm_mma<<<dim3(1, M / 128), 256, GSMEM>>>(hid, w2, fc2_b, x1, out, M, 128, 512, 2);
}